// round 4
// baseline (speedup 1.0000x reference)
#include <cuda_runtime.h>
#include <math.h>

#define NNODES 8192
#define NFEAT  512
#define NHID   256
#define NCLASS 16
#define MAXNB  512
#define ALPHA  0.01f
#define CATW   (NHID + NCLASS)   // 272

// ---------------- scratch (device globals: no allocation allowed) ----------
static __device__ float g_XW1[NNODES * NHID];   // x @ W1
static __device__ float g_H1 [NNODES * NHID];   // relu(spmm + b1)
static __device__ float g_WH [NNODES * NHID];   // h1 @ Wa
static __device__ float g_AO [NNODES * NHID];   // elu(h_prime)
static __device__ float g_T  [NNODES * NCLASS]; // a_out @ W3
static __device__ float g_f1 [NNODES];
static __device__ float g_f2 [NNODES];
static __device__ int   g_colidx[NNODES * MAXNB];
static __device__ int   g_rowlen[NNODES];

// ---------------- CSR build: deterministic two-pass with block scan --------
// One block per row, 256 threads; thread t owns 32 contiguous columns.
__global__ void k_csr(const int* __restrict__ adj) {
    int row = blockIdx.x, t = threadIdx.x;
    const int4* ar = (const int4*)(adj + (size_t)row * NNODES);
    int base4 = t * 8;  // 8 int4 = 32 ints per thread, contiguous

    int cnt = 0;
#pragma unroll
    for (int i = 0; i < 8; i++) {
        int4 v = ar[base4 + i];
        cnt += (v.x != 0) + (v.y != 0) + (v.z != 0) + (v.w != 0);
    }

    // inclusive warp scan
    int lane = t & 31, w = t >> 5;
    int inc = cnt;
#pragma unroll
    for (int o = 1; o < 32; o <<= 1) {
        int v = __shfl_up_sync(0xffffffffu, inc, o);
        if (lane >= o) inc += v;
    }
    __shared__ int wsum[8];
    if (lane == 31) wsum[w] = inc;
    __syncthreads();
    int wbase = 0;
#pragma unroll
    for (int i = 0; i < 8; i++) if (i < w) wbase += wsum[i];
    int pos = wbase + inc - cnt;  // exclusive prefix for this thread

    int* outp = g_colidx + (size_t)row * MAXNB;
#pragma unroll
    for (int i = 0; i < 8; i++) {
        int4 v = ar[base4 + i];       // L1 hit (re-read of same 32 KB row)
        int idx = (base4 + i) * 4;
        if (v.x && pos < MAXNB) outp[pos++] = idx;
        if (v.y && pos < MAXNB) outp[pos++] = idx + 1;
        if (v.z && pos < MAXNB) outp[pos++] = idx + 2;
        if (v.w && pos < MAXNB) outp[pos++] = idx + 3;
    }
    if (t == 255) {
        int tot = wbase + inc;
        g_rowlen[row] = tot > MAXNB ? MAXNB : tot;
    }
}

// ---------------- fp32 tiled GEMM: C[M,Nc] = A[M,K] @ B[K,Nc] --------------
// BM=BN=64, BK=16, 256 threads, 4x4 per-thread microtile. Dims divisible.
__global__ void k_sgemm(const float* __restrict__ A, const float* __restrict__ B,
                        float* __restrict__ C, int M, int Nc, int K) {
    __shared__ float As[16][64];
    __shared__ float Bs[16][64];
    int tid = threadIdx.x;
    int tcol = tid & 15, trow = tid >> 4;
    int rb = blockIdx.y << 6, cb = blockIdx.x << 6;
    float acc[4][4] = {};

    for (int k0 = 0; k0 < K; k0 += 16) {
#pragma unroll
        for (int i = tid; i < 1024; i += 256) {
            int r = i >> 4, c = i & 15;
            As[c][r] = A[(size_t)(rb + r) * K + k0 + c];
        }
#pragma unroll
        for (int i = tid; i < 1024; i += 256) {
            int r = i >> 6, c = i & 63;
            Bs[r][c] = B[(size_t)(k0 + r) * Nc + cb + c];
        }
        __syncthreads();
#pragma unroll
        for (int k = 0; k < 16; k++) {
            float ra[4], rv[4];
#pragma unroll
            for (int m = 0; m < 4; m++) ra[m] = As[k][(trow << 2) + m];
#pragma unroll
            for (int n = 0; n < 4; n++) rv[n] = Bs[k][(tcol << 2) + n];
#pragma unroll
            for (int m = 0; m < 4; m++)
#pragma unroll
                for (int n = 0; n < 4; n++) acc[m][n] += ra[m] * rv[n];
        }
        __syncthreads();
    }
#pragma unroll
    for (int m = 0; m < 4; m++) {
        int r = rb + (trow << 2) + m;
#pragma unroll
        for (int n = 0; n < 4; n++)
            C[(size_t)r * Nc + cb + (tcol << 2) + n] = acc[m][n];
    }
}

// ---------------- spmm1 + bias + relu: h1 = relu(adj @ XW1 + b1) ----------
// One block per row, thread t = column t. Also writes h1 to concat output.
__global__ void k_spmm_relu(const float* __restrict__ b1, float* __restrict__ cat) {
    int row = blockIdx.x, t = threadIdx.x;
    __shared__ int nb[MAXNB];
    int L = g_rowlen[row];
    const int* ci = g_colidx + (size_t)row * MAXNB;
    for (int i = t; i < L; i += 256) nb[i] = ci[i];
    __syncthreads();

    float a0 = 0.f, a1 = 0.f, a2 = 0.f, a3 = 0.f;
    int i = 0;
    for (; i + 4 <= L; i += 4) {
        a0 += g_XW1[(size_t)nb[i]     * NHID + t];
        a1 += g_XW1[(size_t)nb[i + 1] * NHID + t];
        a2 += g_XW1[(size_t)nb[i + 2] * NHID + t];
        a3 += g_XW1[(size_t)nb[i + 3] * NHID + t];
    }
    float acc = (a0 + a1) + (a2 + a3);
    for (; i < L; i++) acc += g_XW1[(size_t)nb[i] * NHID + t];

    float h = acc + b1[t];
    h = h > 0.f ? h : 0.f;
    g_H1[(size_t)row * NHID + t] = h;
    cat[(size_t)row * CATW + t] = h;   // feat part of concat output
}

// ---------------- f1/f2: per-row dots of WH with a_vec halves --------------
__global__ void k_f(const float* __restrict__ a_vec) {
    int w = threadIdx.x >> 5, lane = threadIdx.x & 31;
    int row = blockIdx.x * 8 + w;
    const float* wr = g_WH + (size_t)row * NHID;
    float s1 = 0.f, s2 = 0.f;
    for (int c = lane; c < NHID; c += 32) {
        float v = wr[c];
        s1 += v * a_vec[c];
        s2 += v * a_vec[NHID + c];
    }
#pragma unroll
    for (int o = 16; o; o >>= 1) {
        s1 += __shfl_xor_sync(0xffffffffu, s1, o);
        s2 += __shfl_xor_sync(0xffffffffu, s2, o);
    }
    if (!lane) { g_f1[row] = s1; g_f2[row] = s2; }
}

// ---------------- attention + h_prime + elu, fused per row -----------------
__global__ void k_attn(float* __restrict__ attn) {
    int row = blockIdx.x, t = threadIdx.x;
    __shared__ int   nb[MAXNB];
    __shared__ float pe[MAXNB];
    __shared__ float red[8];
    int L = g_rowlen[row];
    const int* ci = g_colidx + (size_t)row * MAXNB;
    for (int i = t; i < L; i += 256) nb[i] = ci[i];
    __syncthreads();

    float fi = g_f1[row];
    float mx = -1e30f;
    for (int i = t; i < L; i += 256) {
        float e = fi + g_f2[nb[i]];
        e = e > 0.f ? e : ALPHA * e;     // leaky_relu
        pe[i] = e;
        mx = fmaxf(mx, e);
    }
    int lane = t & 31, w = t >> 5;
#pragma unroll
    for (int o = 16; o; o >>= 1) mx = fmaxf(mx, __shfl_xor_sync(0xffffffffu, mx, o));
    if (!lane) red[w] = mx;
    __syncthreads();
    mx = red[0];
#pragma unroll
    for (int i = 1; i < 8; i++) mx = fmaxf(mx, red[i]);
    __syncthreads();                      // protect red before reuse

    float s = 0.f;
    for (int i = t; i < L; i += 256) {
        float p = expf(pe[i] - mx);
        pe[i] = p;
        s += p;
    }
#pragma unroll
    for (int o = 16; o; o >>= 1) s += __shfl_xor_sync(0xffffffffu, s, o);
    if (!lane) red[w] = s;
    __syncthreads();
    float tot = 0.f;
#pragma unroll
    for (int i = 0; i < 8; i++) tot += red[i];
    float inv = 1.f / tot;

    for (int i = t; i < L; i += 256) {
        float p = pe[i] * inv;
        pe[i] = p;
        attn[(size_t)row * NNODES + nb[i]] = p;  // dense attention output
    }
    __syncthreads();

    // h_prime[row, t] = sum_j p_j * WH[j, t], then elu
    float a0 = 0.f, a1 = 0.f, a2 = 0.f, a3 = 0.f;
    int i = 0;
    for (; i + 4 <= L; i += 4) {
        a0 += pe[i]     * g_WH[(size_t)nb[i]     * NHID + t];
        a1 += pe[i + 1] * g_WH[(size_t)nb[i + 1] * NHID + t];
        a2 += pe[i + 2] * g_WH[(size_t)nb[i + 2] * NHID + t];
        a3 += pe[i + 3] * g_WH[(size_t)nb[i + 3] * NHID + t];
    }
    float acc = (a0 + a1) + (a2 + a3);
    for (; i < L; i++) acc += pe[i] * g_WH[(size_t)nb[i] * NHID + t];

    g_AO[(size_t)row * NHID + t] = acc > 0.f ? acc : expm1f(acc);  // elu
}

// ---------------- T = AO @ W3 (K=256, Nc=16) -------------------------------
// 256 threads = 16 rows x 16 cols; W3 staged in shared.
__global__ void k_gemm3(const float* __restrict__ W3) {
    __shared__ float sW[NHID * NCLASS];
    int tx = threadIdx.x & 15, ty = threadIdx.x >> 4;
    int row = blockIdx.x * 16 + ty;
    for (int i = threadIdx.x; i < NHID * NCLASS; i += 256) sW[i] = W3[i];
    __syncthreads();

    const float* ar = g_AO + (size_t)row * NHID;
    float a0 = 0.f, a1 = 0.f, a2 = 0.f, a3 = 0.f;
#pragma unroll 4
    for (int k = 0; k < NHID; k += 4) {
        a0 += ar[k]     * sW[k       * NCLASS + tx];
        a1 += ar[k + 1] * sW[(k + 1) * NCLASS + tx];
        a2 += ar[k + 2] * sW[(k + 2) * NCLASS + tx];
        a3 += ar[k + 3] * sW[(k + 3) * NCLASS + tx];
    }
    g_T[(size_t)row * NCLASS + tx] = (a0 + a1) + (a2 + a3);
}

// ---------------- out = spmm(adj, T) + b3; sigmoid + concat tail -----------
__global__ void k_out(const float* __restrict__ b3, float* __restrict__ sig,
                      float* __restrict__ cat) {
    int tx = threadIdx.x & 15, g = threadIdx.x >> 4;
    int row = blockIdx.x * 16 + g;
    int L = g_rowlen[row];
    const int* ci = g_colidx + (size_t)row * MAXNB;
    float a0 = 0.f, a1 = 0.f;
    int i = 0;
    for (; i + 2 <= L; i += 2) {
        a0 += g_T[(size_t)ci[i]     * NCLASS + tx];
        a1 += g_T[(size_t)ci[i + 1] * NCLASS + tx];
    }
    float acc = a0 + a1;
    for (; i < L; i++) acc += g_T[(size_t)ci[i] * NCLASS + tx];

    float o = acc + b3[tx];
    cat[(size_t)row * CATW + NHID + tx] = o;             // concat tail
    sig[(size_t)row * NCLASS + tx] = 1.f / (1.f + expf(-o));
}

// ---------------- launch ---------------------------------------------------
extern "C" void kernel_launch(void* const* d_in, const int* in_sizes, int n_in,
                              void* d_out, int out_size) {
    const float* x     = (const float*)d_in[0];
    const int*   adj   = (const int*)  d_in[1];
    const float* W1    = (const float*)d_in[2];
    const float* b1    = (const float*)d_in[3];
    const float* Wa    = (const float*)d_in[4];
    const float* a_vec = (const float*)d_in[5];
    const float* W3    = (const float*)d_in[6];
    const float* b3    = (const float*)d_in[7];

    float* out  = (float*)d_out;
    float* sig  = out;                                   // [N, NCLASS]
    float* attn = out + (size_t)NNODES * NCLASS;         // [N, N]
    float* cat  = attn + (size_t)NNODES * NNODES;        // [N, 272]

    float *pXW1, *pH1, *pWH;
    cudaGetSymbolAddress((void**)&pXW1, g_XW1);
    cudaGetSymbolAddress((void**)&pH1,  g_H1);
    cudaGetSymbolAddress((void**)&pWH,  g_WH);

    // zero the dense attention output (sparse scatter fills nnz later)
    cudaMemsetAsync(attn, 0, (size_t)NNODES * NNODES * sizeof(float));

    k_csr<<<NNODES, 256>>>(adj);
    k_sgemm<<<dim3(NHID / 64, NNODES / 64), 256>>>(x, W1, pXW1, NNODES, NHID, NFEAT);
    k_spmm_relu<<<NNODES, 256>>>(b1, cat);
    k_sgemm<<<dim3(NHID / 64, NNODES / 64), 256>>>(pH1, Wa, pWH, NNODES, NHID, NHID);
    k_f<<<NNODES / 8, 256>>>(a_vec);
    k_attn<<<NNODES, 256>>>(attn);
    k_gemm3<<<NNODES / 16, 256>>>(W3);
    k_out<<<NNODES / 16, 256>>>(b3, sig, cat);
}

// round 7
// speedup vs baseline: 1.2063x; 1.2063x over previous
#include <cuda_runtime.h>
#include <math.h>

#define NNODES 8192
#define NFEAT  512
#define NHID   256
#define NCLASS 16
#define MAXNB  512
#define ALPHA  0.01f
#define CATW   (NHID + NCLASS)   // 272

// fused-K1 grid layout
#define G_GEMM 256     // 64 row-tiles x 4 col-tiles (128x64 tiles)
#define G_ZERO 2048
#define G_CSR  NNODES
#define G_K1   (G_GEMM + G_ZERO + G_CSR)

// ---------------- scratch (device globals: no allocation allowed) ----------
static __device__ float g_XW1[NNODES * NHID];   // x @ W1
static __device__ float g_WH [NNODES * NHID];   // h1 @ Wa
static __device__ float g_AO [NNODES * NHID];   // elu(h_prime)
static __device__ float g_T  [NNODES * NCLASS]; // a_out @ W3
static __device__ float g_f1 [NNODES];
static __device__ float g_f2 [NNODES];
static __device__ int   g_colidx[NNODES * MAXNB];
static __device__ int   g_rowlen[NNODES];

// =======================================================================
// K1 (fused): [0,256) GEMM1 XW1 = x @ W1   (M=8192,K=512,N=256)
//             [256,2304) zero the dense attention output
//             [2304,10496) CSR build (one block per adj row)
// =======================================================================
__global__ void k_fused1(const int* __restrict__ adj,
                         const float* __restrict__ A,   // x
                         const float* __restrict__ B,   // W1
                         float* __restrict__ C,         // XW1
                         float* __restrict__ attnz) {
    __shared__ float As[16][128];   // [k][m]
    __shared__ float Bs[16][64];    // [k][n]
    __shared__ int   wsum[8];
    const int bx = blockIdx.x, tid = threadIdx.x;

    if (bx < G_GEMM) {
        // ---------------- GEMM1: 128x64 tile, BK=16, 8x4 microtile ---------
        const int K = NFEAT, Nc = NHID;
        const int rb = (bx >> 2) << 7;       // row tile * 128
        const int cb = (bx & 3) << 6;        // col tile * 64
        const int lrow = tid >> 1, qh = tid & 1;        // A load map
        const int brow = tid >> 4, bc4 = tid & 15;      // B load map
        const int trow = tid >> 4, tcol = tid & 15;     // compute map
        float acc[8][4] = {};

        for (int k0 = 0; k0 < K; k0 += 16) {
            // load A tile (128x16), store transposed As[k][m]
            const float4* ap = (const float4*)(A + (size_t)(rb + lrow) * K + k0 + qh * 8);
            float4 v0 = ap[0], v1 = ap[1];
            int kb = qh * 8;
            As[kb + 0][lrow] = v0.x; As[kb + 1][lrow] = v0.y;
            As[kb + 2][lrow] = v0.z; As[kb + 3][lrow] = v0.w;
            As[kb + 4][lrow] = v1.x; As[kb + 5][lrow] = v1.y;
            As[kb + 6][lrow] = v1.z; As[kb + 7][lrow] = v1.w;
            // load B tile (16x64)
            *(float4*)&Bs[brow][bc4 * 4] =
                *(const float4*)(B + (size_t)(k0 + brow) * Nc + cb + bc4 * 4);
            __syncthreads();
#pragma unroll
            for (int k = 0; k < 16; k++) {
                float4 ra0 = *(const float4*)&As[k][trow * 8];
                float4 ra1 = *(const float4*)&As[k][trow * 8 + 4];
                float4 rv  = *(const float4*)&Bs[k][tcol * 4];
                float ra[8] = {ra0.x, ra0.y, ra0.z, ra0.w, ra1.x, ra1.y, ra1.z, ra1.w};
                float rvv[4] = {rv.x, rv.y, rv.z, rv.w};
#pragma unroll
                for (int m = 0; m < 8; m++)
#pragma unroll
                    for (int n = 0; n < 4; n++) acc[m][n] += ra[m] * rvv[n];
            }
            __syncthreads();
        }
#pragma unroll
        for (int m = 0; m < 8; m++) {
            int r = rb + trow * 8 + m;
            float4 o = {acc[m][0], acc[m][1], acc[m][2], acc[m][3]};
            *(float4*)(C + (size_t)r * Nc + cb + tcol * 4) = o;
        }
    } else if (bx < G_GEMM + G_ZERO) {
        // ---------------- zero attention buffer ----------------------------
        const int zb = bx - G_GEMM;
        float4* p = (float4*)attnz + (size_t)zb * 8192;
        float4 z = {0.f, 0.f, 0.f, 0.f};
#pragma unroll
        for (int i = 0; i < 32; i++) p[i * 256 + tid] = z;
    } else {
        // ---------------- CSR build (deterministic two-pass) ---------------
        const int row = bx - (G_GEMM + G_ZERO);
        const int4* ar = (const int4*)(adj + (size_t)row * NNODES);
        const int base4 = tid * 8;

        int cnt = 0;
#pragma unroll
        for (int i = 0; i < 8; i++) {
            int4 v = ar[base4 + i];
            cnt += (v.x != 0) + (v.y != 0) + (v.z != 0) + (v.w != 0);
        }
        int lane = tid & 31, w = tid >> 5;
        int inc = cnt;
#pragma unroll
        for (int o = 1; o < 32; o <<= 1) {
            int v = __shfl_up_sync(0xffffffffu, inc, o);
            if (lane >= o) inc += v;
        }
        if (lane == 31) wsum[w] = inc;
        __syncthreads();
        int wbase = 0;
#pragma unroll
        for (int i = 0; i < 8; i++) if (i < w) wbase += wsum[i];
        int pos = wbase + inc - cnt;

        int* outp = g_colidx + (size_t)row * MAXNB;
#pragma unroll
        for (int i = 0; i < 8; i++) {
            int4 v = ar[base4 + i];   // L1 re-hit
            int idx = (base4 + i) * 4;
            if (v.x && pos < MAXNB) outp[pos++] = idx;
            if (v.y && pos < MAXNB) outp[pos++] = idx + 1;
            if (v.z && pos < MAXNB) outp[pos++] = idx + 2;
            if (v.w && pos < MAXNB) outp[pos++] = idx + 3;
        }
        if (tid == 255) {
            int tot = wbase + inc;
            g_rowlen[row] = tot > MAXNB ? MAXNB : tot;
        }
    }
}

// =======================================================================
// K2 (fused): per 32-row block:
//   gather: H1 = relu(adj @ XW1 + b1)  -> smem (+ concat head output)
//   GEMM:   WH = H1 @ Wa               -> g_WH
//   f:      f1/f2 = WH . a_vec halves  -> g_f1/g_f2 (warp-local reduce)
// =======================================================================
__global__ void k_spmm_wh(const float* __restrict__ b1,
                          const float* __restrict__ Wa,
                          const float* __restrict__ a_vec,
                          float* __restrict__ cat) {
    __shared__ float H1s[32][NHID];   // 32 KB
    __shared__ float Ws[8][NHID];     // 8 KB
    const int tid = threadIdx.x;
    const int row0 = blockIdx.x * 32;

    // ---- gather phase: thread t = hidden column t ----
    const float bb = b1[tid];
    for (int r = 0; r < 32; r++) {
        const int row = row0 + r;
        const int L = g_rowlen[row];
        const int* ci = g_colidx + (size_t)row * MAXNB;
        float a0 = 0.f, a1 = 0.f, a2 = 0.f, a3 = 0.f;
        int i = 0;
        for (; i + 8 <= L; i += 8) {
            int n0 = ci[i], n1 = ci[i+1], n2 = ci[i+2], n3 = ci[i+3];
            int n4 = ci[i+4], n5 = ci[i+5], n6 = ci[i+6], n7 = ci[i+7];
            a0 += g_XW1[(size_t)n0 * NHID + tid] + g_XW1[(size_t)n4 * NHID + tid];
            a1 += g_XW1[(size_t)n1 * NHID + tid] + g_XW1[(size_t)n5 * NHID + tid];
            a2 += g_XW1[(size_t)n2 * NHID + tid] + g_XW1[(size_t)n6 * NHID + tid];
            a3 += g_XW1[(size_t)n3 * NHID + tid] + g_XW1[(size_t)n7 * NHID + tid];
        }
        float acc = (a0 + a1) + (a2 + a3);
        for (; i < L; i++) acc += g_XW1[(size_t)ci[i] * NHID + tid];
        float h = acc + bb;
        h = h > 0.f ? h : 0.f;
        H1s[r][tid] = h;
        cat[(size_t)row * CATW + tid] = h;
    }
    __syncthreads();

    // ---- GEMM phase: rows = warp*4+m, cols = {lane*4+j, 128+lane*4+j} ----
    const int lane = tid & 31, warp = tid >> 5;
    float acc2[4][8] = {};
    const int lr = tid >> 5, lc = (tid & 31) * 8;   // Ws load map
    for (int k0 = 0; k0 < NHID; k0 += 8) {
        *(float4*)&Ws[lr][lc]     = *(const float4*)(Wa + (size_t)(k0 + lr) * NHID + lc);
        *(float4*)&Ws[lr][lc + 4] = *(const float4*)(Wa + (size_t)(k0 + lr) * NHID + lc + 4);
        __syncthreads();
#pragma unroll
        for (int k = 0; k < 8; k++) {
            float ra[4];
#pragma unroll
            for (int m = 0; m < 4; m++) ra[m] = H1s[warp * 4 + m][k0 + k];  // warp broadcast
            float4 b0 = *(const float4*)&Ws[k][lane * 4];
            float4 b1v = *(const float4*)&Ws[k][128 + lane * 4];
            float rv[8] = {b0.x, b0.y, b0.z, b0.w, b1v.x, b1v.y, b1v.z, b1v.w};
#pragma unroll
            for (int m = 0; m < 4; m++)
#pragma unroll
                for (int j = 0; j < 8; j++) acc2[m][j] += ra[m] * rv[j];
        }
        __syncthreads();
    }

    // ---- epilogue: write WH, compute f1/f2 via warp reduce ----
    float4 av0 = *(const float4*)(a_vec + lane * 4);
    float4 av1 = *(const float4*)(a_vec + 128 + lane * 4);
    float4 aw0 = *(const float4*)(a_vec + NHID + lane * 4);
    float4 aw1 = *(const float4*)(a_vec + NHID + 128 + lane * 4);
#pragma unroll
    for (int m = 0; m < 4; m++) {
        int row = row0 + warp * 4 + m;
        float4 o0 = {acc2[m][0], acc2[m][1], acc2[m][2], acc2[m][3]};
        float4 o1 = {acc2[m][4], acc2[m][5], acc2[m][6], acc2[m][7]};
        *(float4*)(g_WH + (size_t)row * NHID + lane * 4) = o0;
        *(float4*)(g_WH + (size_t)row * NHID + 128 + lane * 4) = o1;
        float s1 = o0.x*av0.x + o0.y*av0.y + o0.z*av0.z + o0.w*av0.w
                 + o1.x*av1.x + o1.y*av1.y + o1.z*av1.z + o1.w*av1.w;
        float s2 = o0.x*aw0.x + o0.y*aw0.y + o0.z*aw0.z + o0.w*aw0.w
                 + o1.x*aw1.x + o1.y*aw1.y + o1.z*aw1.z + o1.w*aw1.w;
#pragma unroll
        for (int o = 16; o; o >>= 1) {
            s1 += __shfl_xor_sync(0xffffffffu, s1, o);
            s2 += __shfl_xor_sync(0xffffffffu, s2, o);
        }
        if (lane == 0) { g_f1[row] = s1; g_f2[row] = s2; }
    }
}

// ---------------- attention + h_prime + elu, fused per row -----------------
__global__ void k_attn(float* __restrict__ attn) {
    int row = blockIdx.x, t = threadIdx.x;
    __shared__ int   nb[MAXNB];
    __shared__ float pe[MAXNB];
    __shared__ float red[8];
    int L = g_rowlen[row];
    const int* ci = g_colidx + (size_t)row * MAXNB;
    for (int i = t; i < L; i += 256) nb[i] = ci[i];
    __syncthreads();

    float fi = g_f1[row];
    float mx = -1e30f;
    for (int i = t; i < L; i += 256) {
        float e = fi + g_f2[nb[i]];
        e = e > 0.f ? e : ALPHA * e;     // leaky_relu
        pe[i] = e;
        mx = fmaxf(mx, e);
    }
    int lane = t & 31, w = t >> 5;
#pragma unroll
    for (int o = 16; o; o >>= 1) mx = fmaxf(mx, __shfl_xor_sync(0xffffffffu, mx, o));
    if (!lane) red[w] = mx;
    __syncthreads();
    mx = red[0];
#pragma unroll
    for (int i = 1; i < 8; i++) mx = fmaxf(mx, red[i]);
    __syncthreads();

    float s = 0.f;
    for (int i = t; i < L; i += 256) {
        float p = expf(pe[i] - mx);
        pe[i] = p;
        s += p;
    }
#pragma unroll
    for (int o = 16; o; o >>= 1) s += __shfl_xor_sync(0xffffffffu, s, o);
    if (!lane) red[w] = s;
    __syncthreads();
    float tot = 0.f;
#pragma unroll
    for (int i = 0; i < 8; i++) tot += red[i];
    float inv = 1.f / tot;

    for (int i = t; i < L; i += 256) {
        float p = pe[i] * inv;
        pe[i] = p;
        attn[(size_t)row * NNODES + nb[i]] = p;  // sparse scatter (buffer pre-zeroed)
    }
    __syncthreads();

    // h_prime[row, t] = sum_j p_j * WH[j, t], then elu  (8-way unrolled)
    float a0 = 0.f, a1 = 0.f, a2 = 0.f, a3 = 0.f;
    int i = 0;
    for (; i + 8 <= L; i += 8) {
        a0 += pe[i]   * g_WH[(size_t)nb[i]   * NHID + t]
            + pe[i+4] * g_WH[(size_t)nb[i+4] * NHID + t];
        a1 += pe[i+1] * g_WH[(size_t)nb[i+1] * NHID + t]
            + pe[i+5] * g_WH[(size_t)nb[i+5] * NHID + t];
        a2 += pe[i+2] * g_WH[(size_t)nb[i+2] * NHID + t]
            + pe[i+6] * g_WH[(size_t)nb[i+6] * NHID + t];
        a3 += pe[i+3] * g_WH[(size_t)nb[i+3] * NHID + t]
            + pe[i+7] * g_WH[(size_t)nb[i+7] * NHID + t];
    }
    float acc = (a0 + a1) + (a2 + a3);
    for (; i < L; i++) acc += pe[i] * g_WH[(size_t)nb[i] * NHID + t];

    g_AO[(size_t)row * NHID + t] = acc > 0.f ? acc : expm1f(acc);  // elu
}

// ---------------- T = AO @ W3 (K=256, Nc=16) -------------------------------
__global__ void k_gemm3(const float* __restrict__ W3) {
    __shared__ float sW[NHID * NCLASS];
    int tx = threadIdx.x & 15, ty = threadIdx.x >> 4;
    int row = blockIdx.x * 16 + ty;
    for (int i = threadIdx.x; i < NHID * NCLASS; i += 256) sW[i] = W3[i];
    __syncthreads();

    const float* ar = g_AO + (size_t)row * NHID;
    float a0 = 0.f, a1 = 0.f, a2 = 0.f, a3 = 0.f;
#pragma unroll 4
    for (int k = 0; k < NHID; k += 4) {
        a0 += ar[k]     * sW[k       * NCLASS + tx];
        a1 += ar[k + 1] * sW[(k + 1) * NCLASS + tx];
        a2 += ar[k + 2] * sW[(k + 2) * NCLASS + tx];
        a3 += ar[k + 3] * sW[(k + 3) * NCLASS + tx];
    }
    g_T[(size_t)row * NCLASS + tx] = (a0 + a1) + (a2 + a3);
}

// ---------------- out = spmm(adj, T) + b3; sigmoid + concat tail -----------
__global__ void k_out(const float* __restrict__ b3, float* __restrict__ sig,
                      float* __restrict__ cat) {
    int tx = threadIdx.x & 15, g = threadIdx.x >> 4;
    int row = blockIdx.x * 16 + g;
    int L = g_rowlen[row];
    const int* ci = g_colidx + (size_t)row * MAXNB;
    float a0 = 0.f, a1 = 0.f;
    int i = 0;
    for (; i + 2 <= L; i += 2) {
        a0 += g_T[(size_t)ci[i]     * NCLASS + tx];
        a1 += g_T[(size_t)ci[i + 1] * NCLASS + tx];
    }
    float acc = a0 + a1;
    for (; i < L; i++) acc += g_T[(size_t)ci[i] * NCLASS + tx];

    float o = acc + b3[tx];
    cat[(size_t)row * CATW + NHID + tx] = o;
    sig[(size_t)row * NCLASS + tx] = 1.f / (1.f + expf(-o));
}

// ---------------- launch ---------------------------------------------------
extern "C" void kernel_launch(void* const* d_in, const int* in_sizes, int n_in,
                              void* d_out, int out_size) {
    const float* x     = (const float*)d_in[0];
    const int*   adj   = (const int*)  d_in[1];
    const float* W1    = (const float*)d_in[2];
    const float* b1    = (const float*)d_in[3];
    const float* Wa    = (const float*)d_in[4];
    const float* a_vec = (const float*)d_in[5];
    const float* W3    = (const float*)d_in[6];
    const float* b3    = (const float*)d_in[7];

    float* out  = (float*)d_out;
    float* sig  = out;                                   // [N, NCLASS]
    float* attn = out + (size_t)NNODES * NCLASS;         // [N, N]
    float* cat  = attn + (size_t)NNODES * NNODES;        // [N, 272]

    float* pXW1;
    cudaGetSymbolAddress((void**)&pXW1, g_XW1);

    k_fused1<<<G_K1, 256>>>(adj, x, W1, pXW1, attn);     // GEMM1 + zero + CSR
    k_spmm_wh<<<NNODES / 32, 256>>>(b1, Wa, a_vec, cat); // spmm+relu, GEMM2, f1/f2
    k_attn<<<NNODES, 256>>>(attn);
    k_gemm3<<<NNODES / 16, 256>>>(W3);
    k_out<<<NNODES / 16, 256>>>(b3, sig, cat);
}